// round 6
// baseline (speedup 1.0000x reference)
#include <cuda_runtime.h>

#define HOP    256
#define NB     128
#define TFR    1001
#define LOUT   256000
#define NPAIR  501            // ceil(1001/2)
#define PADI(i) ((i) + ((i) >> 4))

// ---- packed f32x2 ops (Blackwell) ----
__device__ __forceinline__ float2 padd(float2 a, float2 b) {
    float2 r;
    asm("add.rn.f32x2 %0, %1, %2;"
        : "=l"(reinterpret_cast<unsigned long long&>(r))
        : "l"(reinterpret_cast<unsigned long long&>(a)),
          "l"(reinterpret_cast<unsigned long long&>(b)));
    return r;
}
__device__ __forceinline__ float2 psub(float2 a, float2 b) {
    float2 r;
    asm("sub.rn.f32x2 %0, %1, %2;"
        : "=l"(reinterpret_cast<unsigned long long&>(r))
        : "l"(reinterpret_cast<unsigned long long&>(a)),
          "l"(reinterpret_cast<unsigned long long&>(b)));
    return r;
}
__device__ __forceinline__ float2 cmul(float2 a, float2 b) {
    return make_float2(fmaf(a.x, b.x, -a.y * b.y), fmaf(a.x, b.y, a.y * b.x));
}

// 4-digit base-4 reversal of an 8-bit value
__device__ __forceinline__ int rev8(int x) {
    return ((x & 3) << 6) | ((x & 12) << 2) | ((x >> 2) & 12) | ((x >> 6) & 3);
}

// DIF radix-4 butterfly, post-twiddles
template<bool TW>
__device__ __forceinline__ void bf_dif(float2& a, float2& b, float2& c, float2& d, float2 w1) {
    float2 t0 = padd(a, c), t1 = psub(a, c), t2 = padd(b, d);
    float2 t3 = make_float2(b.y - d.y, d.x - b.x);       // -i*(b-d)
    a = padd(t0, t2);
    float2 o1 = padd(t1, t3), o2 = psub(t0, t2), o3 = psub(t1, t3);
    if (TW) {
        float2 w2 = cmul(w1, w1), w3 = cmul(w2, w1);
        b = cmul(o1, w1); c = cmul(o2, w2); d = cmul(o3, w3);
    } else { b = o1; c = o2; d = o3; }
}

// DIT radix-4 butterfly, pre-twiddles
template<bool TW>
__device__ __forceinline__ void bf_dit(float2& a, float2& b, float2& c, float2& d, float2 w1) {
    if (TW) {
        float2 w2 = cmul(w1, w1), w3 = cmul(w2, w1);
        b = cmul(b, w1); c = cmul(c, w2); d = cmul(d, w3);
    }
    float2 t0 = padd(a, c), t1 = psub(a, c), t2 = padd(b, d), t3 = psub(b, d);
    a = padd(t0, t2);
    c = psub(t0, t2);
    b = make_float2(t1.x + t3.y, t1.y - t3.x);  // t1 - i*t3
    d = make_float2(t1.x - t3.y, t1.y + t3.x);  // t1 + i*t3
}

// W[k] = gp*Zk + gm*conj(Zm); returns conj(W)
__device__ __forceinline__ float2 combW(float g0, float g1, float2 Zk, float2 Zm) {
    float gp = 0.5f * (g0 + g1), gm = 0.5f * (g0 - g1);
    return make_float2(fmaf(gp, Zk.x, gm * Zm.x),
                       fmaf(-gp, Zk.y, gm * Zm.y));
}

// register-local spectral combine for quad pair (kappa, 256-kappa), kappa in [1,127]
__device__ __forceinline__ void combine_pair(float2* ra, float2* rb, int kappa,
                                             const float* F0, const float* F1)
{
    float2 a0 = ra[0], a1 = ra[1], a2 = ra[2], a3 = ra[3];
    float2 b0 = rb[0], b1 = rb[1], b2 = rb[2], b3 = rb[3];
    int band0 = (kappa - 1) >> 2;        // mk = kappa
    int band1 = (255 + kappa) >> 2;      // mk = 256+kappa
    int band2 = (511 - kappa) >> 2;      // mk = 512-kappa
    int band3 = (255 - kappa) >> 2;      // mk = 256-kappa
    float g00 = F0[band0], g10 = F1[band0];
    float g01 = F0[band1], g11 = F1[band1];
    float g02 = F0[band2], g12 = F1[band2];
    float g03 = F0[band3], g13 = F1[band3];
    ra[0] = combW(g00, g10, a0, b3);
    ra[1] = combW(g01, g11, a1, b2);
    ra[2] = combW(g02, g12, a2, b1);
    ra[3] = combW(g03, g13, a3, b0);
    rb[0] = combW(g03, g13, b0, a3);
    rb[1] = combW(g02, g12, b1, a2);
    rb[2] = combW(g01, g11, b2, a1);
    rb[3] = combW(g00, g10, b3, a0);
}

#define BARS() asm volatile("bar.sync %0, 64;" :: "r"(sub + 1) : "memory")

__global__ __launch_bounds__(128, 6)
void filtered_noise_kernel(const float* __restrict__ fb,     // (16,1,128,1001)
                           const float* __restrict__ noise,  // (16,1,256000)
                           float* __restrict__ out)          // (16,1,256000)
{
    __shared__ float2 bufA[2][PADI(1023) + 1];   // single exchange buffer / pipeline
    __shared__ float2 tw[256];
    __shared__ float  F[2][2][NB];
    __shared__ float  wint[1024];       // Hann * (1/1024)

    const int tid = threadIdx.x;
    const int sub = tid >> 6;
    const int j   = tid & 63;
    const int b   = blockIdx.y;
    const int pr  = blockIdx.x * 2 + sub;

    #pragma unroll
    for (int u = tid; u < 256; u += 128) {
        float sn, cs;
        sincospif(-(float)u * (1.0f / 512.0f), &sn, &cs);
        tw[u] = make_float2(cs, sn);
    }
    #pragma unroll
    for (int idx = tid; idx < 1024; idx += 128)
        wint[idx] = 0.5f * (1.0f - cospif((float)(2 * idx) * (1.0f / 1023.0f)))
                  * (1.0f / 1024.0f);
    __syncthreads();
    if (pr >= NPAIR) return;

    const int  t0 = 2 * pr;
    const bool v1 = (t0 + 1) < TFR;

    float* F0 = F[sub][0];
    float* F1 = F[sub][1];
    #pragma unroll
    for (int u = j; u < NB; u += 64) {
        F0[u] = fb[(b * NB + u) * TFR + t0];
        F1[u] = v1 ? fb[(b * NB + u) * TFR + t0 + 1] : 0.0f;
    }

    float2* BA = bufA[sub];
    const int    base0 = t0 * HOP - 512;
    const size_t nOff  = (size_t)b * LOUT;
    const bool interior = (base0 >= 0) && (base0 + 1280 <= LOUT);

    // ---- load: layout A, p = j + 64m; z = frame(t0) + i*frame(t1) ----
    float2 r[16];
    if (interior) {
        const float* np = noise + nOff + base0 + j;
        #pragma unroll
        for (int m = 0; m < 16; m++) {
            float xa = np[64 * m];
            float xb = np[64 * m + 256];
            r[m] = make_float2(fmaf(xa, 2.0f, -1.0f), fmaf(xb, 2.0f, -1.0f));
        }
    } else {
        #pragma unroll
        for (int m = 0; m < 16; m++) {
            int s0 = base0 + j + 64 * m;
            int s1 = s0 + HOP;
            float xa = (s0 >= 0 && s0 < LOUT) ? fmaf(noise[nOff + s0], 2.0f, -1.0f) : 0.0f;
            float xb = (v1 && s1 >= 0 && s1 < LOUT) ? fmaf(noise[nOff + s1], 2.0f, -1.0f) : 0.0f;
            r[m] = make_float2(xa, xb);
        }
    }

    // ================= forward FFT (DIF) =================
    #pragma unroll
    for (int m0 = 0; m0 < 4; m0++)          // stage 0: Q=256
        bf_dif<true>(r[m0], r[m0 + 4], r[m0 + 8], r[m0 + 12], tw[j + 64 * m0]);
    {
        float2 w1 = tw[j << 2];             // stage 1: Q=64
        #pragma unroll
        for (int v = 0; v < 4; v++)
            bf_dif<true>(r[4*v], r[4*v + 1], r[4*v + 2], r[4*v + 3], w1);
    }
    #pragma unroll
    for (int m = 0; m < 16; m++) BA[PADI(j + 64 * m)] = r[m];
    BARS();
    // LD1: each thread reads the set it will later rewrite (no cross-thread WAR)
    #pragma unroll
    for (int m = 0; m < 16; m++) r[m] = BA[PADI((j & 3) + 64 * (j >> 2) + 4 * m)];

    #pragma unroll
    for (int m0 = 0; m0 < 4; m0++)          // stage 2: Q=16
        bf_dif<true>(r[m0], r[m0 + 4], r[m0 + 8], r[m0 + 12], tw[((j & 3) + 4 * m0) << 4]);
    {
        float2 w1 = tw[(j & 3) << 6];       // stage 3: Q=4
        #pragma unroll
        for (int v = 0; v < 4; v++)
            bf_dif<true>(r[4*v], r[4*v + 1], r[4*v + 2], r[4*v + 3], w1);
    }
    // ST2 writes exactly the addresses this thread just read in LD1
    #pragma unroll
    for (int m = 0; m < 16; m++) BA[PADI((j & 3) + 64 * (j >> 2) + 4 * m)] = r[m];
    BARS();

    // ---- paired-quad gather: thread gets quad pairs (ka,256-ka), (kb,255-2j) ----
    const int ka  = 2 * j;
    const int kaS = (j == 0) ? 128 : 256 - 2 * j;
    const int kb  = 2 * j + 1;
    const int kbS = 255 - 2 * j;
    int adr[4];
    {
        int q0 = rev8(ka), q1 = rev8(kaS), q2 = rev8(kb), q3 = rev8(kbS);
        adr[0] = 4 * q0 + (q0 >> 2);
        adr[1] = 4 * q1 + (q1 >> 2);
        adr[2] = 4 * q2 + (q2 >> 2);
        adr[3] = 4 * q3 + (q3 >> 2);
    }
    #pragma unroll
    for (int v = 0; v < 4; v++)
        #pragma unroll
        for (int e = 0; e < 4; e++)
            r[4 * v + e] = BA[adr[v] + e];

    {
        float2 dummy = make_float2(1.0f, 0.0f);  // stage 4: Q=1 (per quad)
        #pragma unroll
        for (int v = 0; v < 4; v++)
            bf_dif<false>(r[4*v], r[4*v + 1], r[4*v + 2], r[4*v + 3], dummy);
    }

    // ---- register-local spectral combine ----
    if (j == 0) {
        // quad kappa=0: bins {0,256,512,768}; DC -> 0; 256<->768; 512 self
        float2 a1 = r[1], a2 = r[2], a3 = r[3];
        float g0a = F0[63],  g1a = F1[63];   // band of mk=256
        float g0b = F0[127], g1b = F1[127];  // band of mk=512
        r[0] = make_float2(0.0f, 0.0f);
        r[1] = combW(g0a, g1a, a1, a3);
        r[2] = combW(g0b, g1b, a2, a2);
        r[3] = combW(g0a, g1a, a3, a1);
        // quad kappa=128 (self-paired): bands {31,95,95,31}, partner 3-e
        float2 b0 = r[4], b1 = r[5], b2 = r[6], b3 = r[7];
        float g0c = F0[31], g1c = F1[31];
        float g0d = F0[95], g1d = F1[95];
        r[4] = combW(g0c, g1c, b0, b3);
        r[5] = combW(g0d, g1d, b1, b2);
        r[6] = combW(g0d, g1d, b2, b1);
        r[7] = combW(g0c, g1c, b3, b0);
    } else {
        combine_pair(r, r + 4, ka, F0, F1);
    }
    combine_pair(r + 8, r + 12, kb, F0, F1);

    // ================= inverse FFT (DIT) =================
    {
        float2 dummy = make_float2(1.0f, 0.0f);  // stage 0: per quad, no twiddle
        #pragma unroll
        for (int v = 0; v < 4; v++)
            bf_dit<false>(r[4*v], r[4*v + 1], r[4*v + 2], r[4*v + 3], dummy);
    }
    // ST3 writes exactly the addresses this thread read in the gather
    #pragma unroll
    for (int v = 0; v < 4; v++)
        #pragma unroll
        for (int e = 0; e < 4; e++)
            BA[adr[v] + e] = r[4 * v + e];
    BARS();
    {
        const int base = 68 * (j >> 2) + (j & 3);
        #pragma unroll
        for (int t = 0; t < 16; t++)
            r[t] = BA[base + 4 * t + (t >> 2)];
    }
    {
        float2 w1 = tw[(j & 3) << 6];       // stage 1: q = p&3 = j&3
        #pragma unroll
        for (int h = 0; h < 4; h++)
            bf_dit<true>(r[4*h], r[4*h + 1], r[4*h + 2], r[4*h + 3], w1);
    }
    #pragma unroll
    for (int i = 0; i < 4; i++)             // stage 2: q = (j&3) + 4i
        bf_dit<true>(r[i], r[i + 4], r[i + 8], r[i + 12], tw[((j & 3) + 4 * i) << 4]);

    // ST4 writes exactly the addresses this thread just read in LD3
    {
        const int base = 68 * (j >> 2) + (j & 3);
        #pragma unroll
        for (int t = 0; t < 16; t++)
            BA[base + 4 * t + (t >> 2)] = r[t];
    }
    BARS();
    #pragma unroll
    for (int m = 0; m < 16; m++)
        r[m] = BA[PADI(j + 64 * m)];

    {
        float2 w1 = tw[j << 2];             // stage 3: q = j
        #pragma unroll
        for (int v = 0; v < 4; v++)
            bf_dit<true>(r[4*v], r[4*v + 1], r[4*v + 2], r[4*v + 3], w1);
    }
    #pragma unroll
    for (int i = 0; i < 4; i++)             // stage 4: q = j + 64i
        bf_dit<true>(r[i], r[i + 4], r[i + 8], r[i + 12], tw[j + 64 * i]);

    // ---- Hann window + overlap-add straight from registers ----
    if (interior) {
        float* op = out + nOff + base0 + j;
        #pragma unroll
        for (int m = 0; m < 16; m++) {
            float win = wint[j + 64 * m];
            atomicAdd(&op[64 * m],        r[m].x * win);
            atomicAdd(&op[64 * m + 256], -r[m].y * win);
        }
    } else {
        #pragma unroll
        for (int m = 0; m < 16; m++) {
            int n = j + 64 * m;
            float win = wint[n];
            int s0 = base0 + n;
            if (s0 >= 0 && s0 < LOUT)
                atomicAdd(&out[nOff + s0], r[m].x * win);
            int s1 = s0 + HOP;
            if (v1 && s1 >= 0 && s1 < LOUT)
                atomicAdd(&out[nOff + s1], -r[m].y * win);
        }
    }
}

extern "C" void kernel_launch(void* const* d_in, const int* in_sizes, int n_in,
                              void* d_out, int out_size)
{
    const float* fb    = (const float*)d_in[0];
    const float* noise = (const float*)d_in[1];
    float* out = (float*)d_out;

    cudaMemsetAsync(out, 0, (size_t)out_size * sizeof(float));

    dim3 grid((NPAIR + 1) / 2, 16);
    filtered_noise_kernel<<<grid, 128>>>(fb, noise, out);
}

// round 7
// speedup vs baseline: 1.5518x; 1.5518x over previous
#include <cuda_runtime.h>

#define HOP    256
#define NB     128
#define TFR    1001
#define LOUT   256000
#define NPAIR  501            // ceil(1001/2)
#define PADI(i) ((i) + ((i) >> 4))

// ---- packed f32x2 ops (Blackwell) ----
__device__ __forceinline__ float2 padd(float2 a, float2 b) {
    float2 r;
    asm("add.rn.f32x2 %0, %1, %2;"
        : "=l"(reinterpret_cast<unsigned long long&>(r))
        : "l"(reinterpret_cast<unsigned long long&>(a)),
          "l"(reinterpret_cast<unsigned long long&>(b)));
    return r;
}
__device__ __forceinline__ float2 psub(float2 a, float2 b) {
    float2 r;
    asm("sub.rn.f32x2 %0, %1, %2;"
        : "=l"(reinterpret_cast<unsigned long long&>(r))
        : "l"(reinterpret_cast<unsigned long long&>(a)),
          "l"(reinterpret_cast<unsigned long long&>(b)));
    return r;
}
__device__ __forceinline__ float2 cmul(float2 a, float2 b) {
    return make_float2(fmaf(a.x, b.x, -a.y * b.y), fmaf(a.x, b.y, a.y * b.x));
}

// 4-digit base-4 reversal of an 8-bit value
__device__ __forceinline__ int rev8(int x) {
    return ((x & 3) << 6) | ((x & 12) << 2) | ((x >> 2) & 12) | ((x >> 6) & 3);
}

// DIF radix-4 butterfly, post-twiddles
template<bool TW>
__device__ __forceinline__ void bf_dif(float2& a, float2& b, float2& c, float2& d, float2 w1) {
    float2 t0 = padd(a, c), t1 = psub(a, c), t2 = padd(b, d);
    float2 t3 = make_float2(b.y - d.y, d.x - b.x);       // -i*(b-d)
    a = padd(t0, t2);
    float2 o1 = padd(t1, t3), o2 = psub(t0, t2), o3 = psub(t1, t3);
    if (TW) {
        float2 w2 = cmul(w1, w1), w3 = cmul(w2, w1);
        b = cmul(o1, w1); c = cmul(o2, w2); d = cmul(o3, w3);
    } else { b = o1; c = o2; d = o3; }
}

// DIT radix-4 butterfly, pre-twiddles
template<bool TW>
__device__ __forceinline__ void bf_dit(float2& a, float2& b, float2& c, float2& d, float2 w1) {
    if (TW) {
        float2 w2 = cmul(w1, w1), w3 = cmul(w2, w1);
        b = cmul(b, w1); c = cmul(c, w2); d = cmul(d, w3);
    }
    float2 t0 = padd(a, c), t1 = psub(a, c), t2 = padd(b, d), t3 = psub(b, d);
    a = padd(t0, t2);
    c = psub(t0, t2);
    b = make_float2(t1.x + t3.y, t1.y - t3.x);  // t1 - i*t3
    d = make_float2(t1.x - t3.y, t1.y + t3.x);  // t1 + i*t3
}

// W[k] = gp*Zk + gm*conj(Zm); returns conj(W)
__device__ __forceinline__ float2 combW(float g0, float g1, float2 Zk, float2 Zm) {
    float gp = 0.5f * (g0 + g1), gm = 0.5f * (g0 - g1);
    return make_float2(fmaf(gp, Zk.x, gm * Zm.x),
                       fmaf(-gp, Zk.y, gm * Zm.y));
}

// register-local spectral combine for quad pair (kappa, 256-kappa), kappa in [1,127]
__device__ __forceinline__ void combine_pair(float2* ra, float2* rb, int kappa,
                                             const float* F0, const float* F1)
{
    float2 a0 = ra[0], a1 = ra[1], a2 = ra[2], a3 = ra[3];
    float2 b0 = rb[0], b1 = rb[1], b2 = rb[2], b3 = rb[3];
    int band0 = (kappa - 1) >> 2;        // mk = kappa
    int band1 = (255 + kappa) >> 2;      // mk = 256+kappa
    int band2 = (511 - kappa) >> 2;      // mk = 512-kappa
    int band3 = (255 - kappa) >> 2;      // mk = 256-kappa
    float g00 = F0[band0], g10 = F1[band0];
    float g01 = F0[band1], g11 = F1[band1];
    float g02 = F0[band2], g12 = F1[band2];
    float g03 = F0[band3], g13 = F1[band3];
    ra[0] = combW(g00, g10, a0, b3);
    ra[1] = combW(g01, g11, a1, b2);
    ra[2] = combW(g02, g12, a2, b1);
    ra[3] = combW(g03, g13, a3, b0);
    rb[0] = combW(g03, g13, b0, a3);
    rb[1] = combW(g02, g12, b1, a2);
    rb[2] = combW(g01, g11, b2, a1);
    rb[3] = combW(g00, g10, b3, a0);
}

#define BARS() asm volatile("bar.sync %0, 64;" :: "r"(sub + 1) : "memory")

__global__ __launch_bounds__(128)
void filtered_noise_kernel(const float* __restrict__ fb,     // (16,1,128,1001)
                           const float* __restrict__ noise,  // (16,1,256000)
                           float* __restrict__ out)          // (16,1,256000)
{
    __shared__ float2 bufA[2][PADI(1023) + 1];   // single exchange buffer / pipeline
    __shared__ float2 tw[256];
    __shared__ float  F[2][2][NB];
    __shared__ float  wint[1024];       // Hann * (1/1024)

    const int tid = threadIdx.x;
    const int sub = tid >> 6;
    const int j   = tid & 63;
    const int b   = blockIdx.y;
    const int pr  = blockIdx.x * 2 + sub;

    #pragma unroll
    for (int u = tid; u < 256; u += 128) {
        float sn, cs;
        sincospif(-(float)u * (1.0f / 512.0f), &sn, &cs);
        tw[u] = make_float2(cs, sn);
    }
    #pragma unroll
    for (int idx = tid; idx < 1024; idx += 128)
        wint[idx] = 0.5f * (1.0f - cospif((float)(2 * idx) * (1.0f / 1023.0f)))
                  * (1.0f / 1024.0f);
    __syncthreads();
    if (pr >= NPAIR) return;

    const int  t0 = 2 * pr;
    const bool v1 = (t0 + 1) < TFR;

    float* F0 = F[sub][0];
    float* F1 = F[sub][1];
    #pragma unroll
    for (int u = j; u < NB; u += 64) {
        F0[u] = fb[(b * NB + u) * TFR + t0];
        F1[u] = v1 ? fb[(b * NB + u) * TFR + t0 + 1] : 0.0f;
    }

    float2* BA = bufA[sub];
    const int    base0 = t0 * HOP - 512;
    const size_t nOff  = (size_t)b * LOUT;
    const bool interior = (base0 >= 0) && (base0 + 1280 <= LOUT);

    // ---- load: layout A, p = j + 64m; z = frame(t0) + i*frame(t1) ----
    float2 r[16];
    if (interior) {
        const float* np = noise + nOff + base0 + j;
        #pragma unroll
        for (int m = 0; m < 16; m++) {
            float xa = np[64 * m];
            float xb = np[64 * m + 256];
            r[m] = make_float2(fmaf(xa, 2.0f, -1.0f), fmaf(xb, 2.0f, -1.0f));
        }
    } else {
        #pragma unroll
        for (int m = 0; m < 16; m++) {
            int s0 = base0 + j + 64 * m;
            int s1 = s0 + HOP;
            float xa = (s0 >= 0 && s0 < LOUT) ? fmaf(noise[nOff + s0], 2.0f, -1.0f) : 0.0f;
            float xb = (v1 && s1 >= 0 && s1 < LOUT) ? fmaf(noise[nOff + s1], 2.0f, -1.0f) : 0.0f;
            r[m] = make_float2(xa, xb);
        }
    }

    // ================= forward FFT (DIF) =================
    #pragma unroll
    for (int m0 = 0; m0 < 4; m0++)          // stage 0: Q=256
        bf_dif<true>(r[m0], r[m0 + 4], r[m0 + 8], r[m0 + 12], tw[j + 64 * m0]);
    {
        float2 w1 = tw[j << 2];             // stage 1: Q=64
        #pragma unroll
        for (int v = 0; v < 4; v++)
            bf_dif<true>(r[4*v], r[4*v + 1], r[4*v + 2], r[4*v + 3], w1);
    }
    #pragma unroll
    for (int m = 0; m < 16; m++) BA[PADI(j + 64 * m)] = r[m];
    BARS();
    // LD1: each thread reads the set it will later rewrite (no cross-thread WAR)
    #pragma unroll
    for (int m = 0; m < 16; m++) r[m] = BA[PADI((j & 3) + 64 * (j >> 2) + 4 * m)];

    #pragma unroll
    for (int m0 = 0; m0 < 4; m0++)          // stage 2: Q=16
        bf_dif<true>(r[m0], r[m0 + 4], r[m0 + 8], r[m0 + 12], tw[((j & 3) + 4 * m0) << 4]);
    {
        float2 w1 = tw[(j & 3) << 6];       // stage 3: Q=4
        #pragma unroll
        for (int v = 0; v < 4; v++)
            bf_dif<true>(r[4*v], r[4*v + 1], r[4*v + 2], r[4*v + 3], w1);
    }
    // ST2 writes exactly the addresses this thread just read in LD1
    #pragma unroll
    for (int m = 0; m < 16; m++) BA[PADI((j & 3) + 64 * (j >> 2) + 4 * m)] = r[m];
    BARS();

    // ---- paired-quad gather: thread gets quad pairs (ka,256-ka), (kb,255-2j) ----
    const int ka  = 2 * j;
    const int kaS = (j == 0) ? 128 : 256 - 2 * j;
    const int kb  = 2 * j + 1;
    const int kbS = 255 - 2 * j;
    int adr[4];
    {
        int q0 = rev8(ka), q1 = rev8(kaS), q2 = rev8(kb), q3 = rev8(kbS);
        adr[0] = 4 * q0 + (q0 >> 2);
        adr[1] = 4 * q1 + (q1 >> 2);
        adr[2] = 4 * q2 + (q2 >> 2);
        adr[3] = 4 * q3 + (q3 >> 2);
    }
    #pragma unroll
    for (int v = 0; v < 4; v++)
        #pragma unroll
        for (int e = 0; e < 4; e++)
            r[4 * v + e] = BA[adr[v] + e];

    {
        float2 dummy = make_float2(1.0f, 0.0f);  // stage 4: Q=1 (per quad)
        #pragma unroll
        for (int v = 0; v < 4; v++)
            bf_dif<false>(r[4*v], r[4*v + 1], r[4*v + 2], r[4*v + 3], dummy);
    }

    // ---- register-local spectral combine ----
    if (j == 0) {
        // quad kappa=0: bins {0,256,512,768}; DC -> 0; 256<->768; 512 self
        float2 a1 = r[1], a2 = r[2], a3 = r[3];
        float g0a = F0[63],  g1a = F1[63];   // band of mk=256
        float g0b = F0[127], g1b = F1[127];  // band of mk=512
        r[0] = make_float2(0.0f, 0.0f);
        r[1] = combW(g0a, g1a, a1, a3);
        r[2] = combW(g0b, g1b, a2, a2);
        r[3] = combW(g0a, g1a, a3, a1);
        // quad kappa=128 (self-paired): bands {31,95,95,31}, partner 3-e
        float2 b0 = r[4], b1 = r[5], b2 = r[6], b3 = r[7];
        float g0c = F0[31], g1c = F1[31];
        float g0d = F0[95], g1d = F1[95];
        r[4] = combW(g0c, g1c, b0, b3);
        r[5] = combW(g0d, g1d, b1, b2);
        r[6] = combW(g0d, g1d, b2, b1);
        r[7] = combW(g0c, g1c, b3, b0);
    } else {
        combine_pair(r, r + 4, ka, F0, F1);
    }
    combine_pair(r + 8, r + 12, kb, F0, F1);

    // ================= inverse FFT (DIT) =================
    {
        float2 dummy = make_float2(1.0f, 0.0f);  // stage 0: per quad, no twiddle
        #pragma unroll
        for (int v = 0; v < 4; v++)
            bf_dit<false>(r[4*v], r[4*v + 1], r[4*v + 2], r[4*v + 3], dummy);
    }
    // ST3 writes exactly the addresses this thread read in the gather
    #pragma unroll
    for (int v = 0; v < 4; v++)
        #pragma unroll
        for (int e = 0; e < 4; e++)
            BA[adr[v] + e] = r[4 * v + e];
    BARS();
    {
        const int base = 68 * (j >> 2) + (j & 3);
        #pragma unroll
        for (int t = 0; t < 16; t++)
            r[t] = BA[base + 4 * t + (t >> 2)];
    }
    {
        float2 w1 = tw[(j & 3) << 6];       // stage 1: q = p&3 = j&3
        #pragma unroll
        for (int h = 0; h < 4; h++)
            bf_dit<true>(r[4*h], r[4*h + 1], r[4*h + 2], r[4*h + 3], w1);
    }
    #pragma unroll
    for (int i = 0; i < 4; i++)             // stage 2: q = (j&3) + 4i
        bf_dit<true>(r[i], r[i + 4], r[i + 8], r[i + 12], tw[((j & 3) + 4 * i) << 4]);

    // ST4 writes exactly the addresses this thread just read in LD3
    {
        const int base = 68 * (j >> 2) + (j & 3);
        #pragma unroll
        for (int t = 0; t < 16; t++)
            BA[base + 4 * t + (t >> 2)] = r[t];
    }
    BARS();
    #pragma unroll
    for (int m = 0; m < 16; m++)
        r[m] = BA[PADI(j + 64 * m)];

    {
        float2 w1 = tw[j << 2];             // stage 3: q = j
        #pragma unroll
        for (int v = 0; v < 4; v++)
            bf_dit<true>(r[4*v], r[4*v + 1], r[4*v + 2], r[4*v + 3], w1);
    }
    #pragma unroll
    for (int i = 0; i < 4; i++)             // stage 4: q = j + 64i
        bf_dit<true>(r[i], r[i + 4], r[i + 8], r[i + 12], tw[j + 64 * i]);

    // ---- Hann window + overlap-add straight from registers ----
    if (interior) {
        float* op = out + nOff + base0 + j;
        #pragma unroll
        for (int m = 0; m < 16; m++) {
            float win = wint[j + 64 * m];
            atomicAdd(&op[64 * m],        r[m].x * win);
            atomicAdd(&op[64 * m + 256], -r[m].y * win);
        }
    } else {
        #pragma unroll
        for (int m = 0; m < 16; m++) {
            int n = j + 64 * m;
            float win = wint[n];
            int s0 = base0 + n;
            if (s0 >= 0 && s0 < LOUT)
                atomicAdd(&out[nOff + s0], r[m].x * win);
            int s1 = s0 + HOP;
            if (v1 && s1 >= 0 && s1 < LOUT)
                atomicAdd(&out[nOff + s1], -r[m].y * win);
        }
    }
}

extern "C" void kernel_launch(void* const* d_in, const int* in_sizes, int n_in,
                              void* d_out, int out_size)
{
    const float* fb    = (const float*)d_in[0];
    const float* noise = (const float*)d_in[1];
    float* out = (float*)d_out;

    cudaMemsetAsync(out, 0, (size_t)out_size * sizeof(float));

    dim3 grid((NPAIR + 1) / 2, 16);
    filtered_noise_kernel<<<grid, 128>>>(fb, noise, out);
}

// round 8
// speedup vs baseline: 1.5708x; 1.0122x over previous
#include <cuda_runtime.h>

#define HOP    256
#define NB     128
#define TFR    1001
#define LOUT   256000
#define NPAIR  501            // ceil(1001/2)

// ---- packed f32x2 ops (Blackwell) ----
__device__ __forceinline__ float2 padd(float2 a, float2 b) {
    float2 r;
    asm("add.rn.f32x2 %0, %1, %2;"
        : "=l"(reinterpret_cast<unsigned long long&>(r))
        : "l"(reinterpret_cast<unsigned long long&>(a)),
          "l"(reinterpret_cast<unsigned long long&>(b)));
    return r;
}
__device__ __forceinline__ float2 psub(float2 a, float2 b) {
    float2 r;
    asm("sub.rn.f32x2 %0, %1, %2;"
        : "=l"(reinterpret_cast<unsigned long long&>(r))
        : "l"(reinterpret_cast<unsigned long long&>(a)),
          "l"(reinterpret_cast<unsigned long long&>(b)));
    return r;
}
__device__ __forceinline__ float2 cmul(float2 a, float2 b) {
    return make_float2(fmaf(a.x, b.x, -a.y * b.y), fmaf(a.x, b.y, a.y * b.x));
}

// Output permutation of the local 32-pt DIF FFT (radix 4,4,2):
// position p = 8a + 2b + c  holds bin  k = a + 4b + 16c
__host__ __device__ constexpr int SIG(int p)  { return (p >> 3) + 4 * ((p >> 1) & 3) + 16 * (p & 1); }
__host__ __device__ constexpr int ISIG(int k) { return 8 * (k & 3) + 2 * ((k >> 2) & 3) + (k >> 4); }

// W_32^k constants, k = 0..21 : (cos(2pi k/32), -sin(2pi k/32))
__device__ __constant__ const float W32R[22] = {
    1.0f, 0.98078528f, 0.92387953f, 0.83146961f, 0.70710678f, 0.55557023f,
    0.38268343f, 0.19509032f, 0.0f, -0.19509032f, -0.38268343f, -0.55557023f,
    -0.70710678f, -0.83146961f, -0.92387953f, -0.98078528f, -1.0f,
    -0.98078528f, -0.92387953f, -0.83146961f, -0.70710678f, -0.55557023f };
__device__ __constant__ const float W32I[22] = {
    0.0f, -0.19509032f, -0.38268343f, -0.55557023f, -0.70710678f, -0.83146961f,
    -0.92387953f, -0.98078528f, -1.0f, -0.98078528f, -0.92387953f, -0.83146961f,
    -0.70710678f, -0.55557023f, -0.38268343f, -0.19509032f, 0.0f,
    0.19509032f, 0.38268343f, 0.55557023f, 0.70710678f, 0.83146961f };

__device__ __forceinline__ void bf_dif3(float2& a, float2& b, float2& c, float2& d,
                                        float2 w1, float2 w2, float2 w3) {
    float2 t0 = padd(a, c), t1 = psub(a, c), t2 = padd(b, d);
    float2 t3 = make_float2(b.y - d.y, d.x - b.x);   // -i*(b-d)
    a = padd(t0, t2);
    float2 o1 = padd(t1, t3), o2 = psub(t0, t2), o3 = psub(t1, t3);
    b = cmul(o1, w1); c = cmul(o2, w2); d = cmul(o3, w3);
}
__device__ __forceinline__ void bf_dif_nt(float2& a, float2& b, float2& c, float2& d) {
    float2 t0 = padd(a, c), t1 = psub(a, c), t2 = padd(b, d);
    float2 t3 = make_float2(b.y - d.y, d.x - b.x);
    a = padd(t0, t2); b = padd(t1, t3); c = psub(t0, t2); d = psub(t1, t3);
}

// In-place 32-pt DIF FFT; natural order in, SIG-permuted out.
__device__ __forceinline__ void fft32(float2 v[32]) {
    // stage 1: radix-4, stride 8, twiddles W_32^{i,2i,3i}
    bf_dif_nt(v[0], v[8], v[16], v[24]);
    #pragma unroll
    for (int i = 1; i < 8; i++)
        bf_dif3(v[i], v[i + 8], v[i + 16], v[i + 24],
                make_float2(W32R[i], W32I[i]),
                make_float2(W32R[2 * i], W32I[2 * i]),
                make_float2(W32R[3 * i], W32I[3 * i]));
    // stage 2: radix-4 in blocks of 8, stride 2, twiddles W_8^{1,2,3}
    #pragma unroll
    for (int blk = 0; blk < 4; blk++) {
        const int s = 8 * blk;
        bf_dif_nt(v[s], v[s + 2], v[s + 4], v[s + 6]);
        bf_dif3(v[s + 1], v[s + 3], v[s + 5], v[s + 7],
                make_float2(W32R[4], W32I[4]),
                make_float2(W32R[8], W32I[8]),
                make_float2(W32R[12], W32I[12]));
    }
    // stage 3: radix-2 pairs
    #pragma unroll
    for (int u = 0; u < 16; u++) {
        float2 a = v[2 * u], b = v[2 * u + 1];
        v[2 * u] = padd(a, b);
        v[2 * u + 1] = psub(a, b);
    }
}

// Multiply v[ISIG(m)] by W_1024^{lane*m} for m=1..31, built from base A1 = W_1024^lane.
__device__ __forceinline__ void twmul(float2 v[32], float2 A1) {
    float2 A2 = cmul(A1, A1);
    float2 A3 = cmul(A2, A1);
    float2 A4 = cmul(A2, A2);
    float2 A5 = cmul(A4, A1);
    float2 A6 = cmul(A4, A2);
    float2 A7 = cmul(A4, A3);
    float2 B8  = cmul(A4, A4);
    float2 B16 = cmul(B8, B8);
    float2 B24 = cmul(B16, B8);
    float2 A[8] = { make_float2(1.f, 0.f), A1, A2, A3, A4, A5, A6, A7 };
    #pragma unroll
    for (int d = 1; d < 8; d++)
        v[ISIG(d)] = cmul(v[ISIG(d)], A[d]);
    v[ISIG(8)]  = cmul(v[ISIG(8)],  B8);
    v[ISIG(16)] = cmul(v[ISIG(16)], B16);
    v[ISIG(24)] = cmul(v[ISIG(24)], B24);
    #pragma unroll
    for (int d = 1; d < 8; d++) {
        v[ISIG(8 + d)]  = cmul(v[ISIG(8 + d)],  cmul(B8,  A[d]));
        v[ISIG(16 + d)] = cmul(v[ISIG(16 + d)], cmul(B16, A[d]));
        v[ISIG(24 + d)] = cmul(v[ISIG(24 + d)], cmul(B24, A[d]));
    }
}

// W[k] = gp*Zk + gm*conj(Zm); returns conj(W)
__device__ __forceinline__ float2 combW(float g0, float g1, float2 Zk, float2 Zm) {
    float gp = 0.5f * (g0 + g1), gm = 0.5f * (g0 - g1);
    return make_float2(fmaf(gp, Zk.x, gm * Zm.x),
                       fmaf(-gp, Zk.y, gm * Zm.y));
}

__device__ __forceinline__ float2 shfl2(float2 v, int src) {
    float2 r;
    r.x = __shfl_sync(0xffffffffu, v.x, src);
    r.y = __shfl_sync(0xffffffffu, v.y, src);
    return r;
}

__global__ __launch_bounds__(128)
void filtered_noise_kernel(const float* __restrict__ fb,     // (16,1,128,1001)
                           const float* __restrict__ noise,  // (16,1,256000)
                           float* __restrict__ out)          // (16,1,256000)
{
    __shared__ float2 tb[4][33 * 32];   // per-warp transpose buffer (33-stride pad)
    __shared__ float2 FP[4][NB];        // per-warp (g0,g1) band gains
    __shared__ float2 tw32s[32];        // W_1024^l, l<32
    __shared__ float  wint[1024];       // Hann * (1/1024)

    const int tid  = threadIdx.x;
    const int wid  = tid >> 5;
    const int lane = tid & 31;
    const int b    = blockIdx.y;
    const int pr   = blockIdx.x * 4 + wid;

    #pragma unroll
    for (int idx = tid; idx < 1024; idx += 128)
        wint[idx] = 0.5f * (1.0f - cospif((float)(2 * idx) * (1.0f / 1023.0f)))
                  * (1.0f / 1024.0f);
    if (tid < 32) {
        float sn, cs;
        sincospif(-(float)tid * (1.0f / 512.0f), &sn, &cs);
        tw32s[tid] = make_float2(cs, sn);
    }
    __syncthreads();
    if (pr >= NPAIR) return;

    const int  t0 = 2 * pr;
    const bool v1 = (t0 + 1) < TFR;

    float2* FPw = FP[wid];
    #pragma unroll
    for (int u = lane; u < NB; u += 32) {
        float g0 = fb[(b * NB + u) * TFR + t0];
        float g1 = v1 ? fb[(b * NB + u) * TFR + t0 + 1] : 0.0f;
        FPw[u] = make_float2(g0, g1);
    }

    float2* tbw = tb[wid];
    const int    base0 = t0 * HOP - 512;
    const size_t nOff  = (size_t)b * LOUT;
    const bool interior = (base0 >= 0) && (base0 + 1280 <= LOUT);
    const float2 A1 = tw32s[lane];

    // ---- load: v[n1] = z[32*n1 + lane], z = frame(t0) + i*frame(t1) ----
    float2 v[32];
    if (interior) {
        const float* np = noise + nOff + base0 + lane;
        #pragma unroll
        for (int n1 = 0; n1 < 32; n1++) {
            float xa = np[32 * n1];
            float xb = np[32 * n1 + HOP];
            v[n1] = make_float2(fmaf(xa, 2.0f, -1.0f), fmaf(xb, 2.0f, -1.0f));
        }
    } else {
        #pragma unroll
        for (int n1 = 0; n1 < 32; n1++) {
            int s0 = base0 + 32 * n1 + lane;
            int s1 = s0 + HOP;
            float xa = (s0 >= 0 && s0 < LOUT) ? fmaf(noise[nOff + s0], 2.0f, -1.0f) : 0.0f;
            float xb = (v1 && s1 >= 0 && s1 < LOUT) ? fmaf(noise[nOff + s1], 2.0f, -1.0f) : 0.0f;
            v[n1] = make_float2(xa, xb);
        }
    }

    // ================= forward four-step FFT =================
    fft32(v);                 // over n1; reg p holds k1 = SIG(p)
    twmul(v, A1);             // *= W_1024^{lane * k1}
    #pragma unroll
    for (int p = 0; p < 32; p++) tbw[33 * SIG(p) + lane] = v[p];
    __syncwarp();
    #pragma unroll
    for (int n2 = 0; n2 < 32; n2++) v[n2] = tbw[33 * lane + n2];
    fft32(v);                 // over n2; thread lane = k1, reg q holds k2 = SIG(q)

    // ================= spectral combine (shuffles) =================
    // bin k = 32*SIG(q) + lane; partner at lane (32-l)&31, reg ISIG(31-SIG(q)).
    // Write combined conj(W) into w[], permuted so w[n1] = spectrum[32*n1 + lane].
    float2 w[32];
    {
        const int pl = (32 - lane) & 31;
        #pragma unroll
        for (int sq = 0; sq < 16; sq++) {
            const int q = ISIG(sq), tq = ISIG(31 - sq);
            float2 pq  = shfl2(v[tq], pl);   // partner value for my bin at reg q
            float2 ptq = shfl2(v[q],  pl);   // partner value for my bin at reg tq
            if (lane != 0) {
                float2 gq  = FPw[(32 * sq + lane - 1) >> 2];
                float2 gtq = FPw[(32 * sq + 31 - lane) >> 2];
                w[sq]      = combW(gq.x,  gq.y,  v[q],  pq);   // w[SIG(q)] = w[sq]
                w[31 - sq] = combW(gtq.x, gtq.y, v[tq], ptq);  // w[SIG(tq)]
            }
        }
        if (lane == 0) {
            // bins k = 32*sq: pairs (sq, 32-sq) thread-local; shared band (32sq-1)>>2
            #pragma unroll
            for (int sq = 1; sq < 16; sq++) {
                const int q = ISIG(sq), q2 = ISIG(32 - sq);
                float2 A = v[q], B = v[q2];
                float2 g = FPw[(32 * sq - 1) >> 2];
                w[sq]      = combW(g.x, g.y, A, B);
                w[32 - sq] = combW(g.x, g.y, B, A);
            }
            float2 g512 = FPw[127];
            w[16] = combW(g512.x, g512.y, v[ISIG(16)], v[ISIG(16)]);
            w[0]  = make_float2(0.0f, 0.0f);
        }
    }

    // ================= inverse four-step (forward FFT of conj spectrum) =================
    fft32(w);                 // over n1
    twmul(w, A1);
    __syncwarp();             // WAR: forward transpose reads done in all lanes
    #pragma unroll
    for (int p = 0; p < 32; p++) tbw[33 * SIG(p) + lane] = w[p];
    __syncwarp();
    #pragma unroll
    for (int n2 = 0; n2 < 32; n2++) v[n2] = tbw[33 * lane + n2];
    fft32(v);                 // reg q: time sample n = 32*SIG(q) + lane (x1024, conj)

    // ---- Hann window + overlap-add ----
    if (interior) {
        float* op = out + nOff + base0 + lane;
        #pragma unroll
        for (int q = 0; q < 32; q++) {
            const int n = 32 * SIG(q) + lane;
            float wn = wint[n];
            atomicAdd(&op[32 * SIG(q)],        v[q].x * wn);
            atomicAdd(&op[32 * SIG(q) + HOP], -v[q].y * wn);
        }
    } else {
        #pragma unroll
        for (int q = 0; q < 32; q++) {
            const int n = 32 * SIG(q) + lane;
            float wn = wint[n];
            int s0 = base0 + n;
            if (s0 >= 0 && s0 < LOUT)
                atomicAdd(&out[nOff + s0], v[q].x * wn);
            int s1 = s0 + HOP;
            if (v1 && s1 >= 0 && s1 < LOUT)
                atomicAdd(&out[nOff + s1], -v[q].y * wn);
        }
    }
}

extern "C" void kernel_launch(void* const* d_in, const int* in_sizes, int n_in,
                              void* d_out, int out_size)
{
    const float* fb    = (const float*)d_in[0];
    const float* noise = (const float*)d_in[1];
    float* out = (float*)d_out;

    cudaMemsetAsync(out, 0, (size_t)out_size * sizeof(float));

    dim3 grid((NPAIR + 3) / 4, 16);
    filtered_noise_kernel<<<grid, 128>>>(fb, noise, out);
}

// round 9
// speedup vs baseline: 1.6350x; 1.0409x over previous
#include <cuda_runtime.h>

#define HOP    256
#define NB     128
#define TFR    1001
#define LOUT   256000
#define NPAIR  501            // ceil(1001/2)

// ---- packed f32x2 ops (Blackwell) ----
__device__ __forceinline__ float2 padd(float2 a, float2 b) {
    float2 r;
    asm("add.rn.f32x2 %0, %1, %2;"
        : "=l"(reinterpret_cast<unsigned long long&>(r))
        : "l"(reinterpret_cast<unsigned long long&>(a)),
          "l"(reinterpret_cast<unsigned long long&>(b)));
    return r;
}
__device__ __forceinline__ float2 psub(float2 a, float2 b) {
    float2 r;
    asm("sub.rn.f32x2 %0, %1, %2;"
        : "=l"(reinterpret_cast<unsigned long long&>(r))
        : "l"(reinterpret_cast<unsigned long long&>(a)),
          "l"(reinterpret_cast<unsigned long long&>(b)));
    return r;
}
__device__ __forceinline__ float2 cmul(float2 a, float2 b) {
    return make_float2(fmaf(a.x, b.x, -a.y * b.y), fmaf(a.x, b.y, a.y * b.x));
}

// Output permutation of the local 32-pt DIF FFT (radix 4,4,2):
// position p = 8a + 2b + c  holds bin  k = a + 4b + 16c
__host__ __device__ constexpr int SIG(int p)  { return (p >> 3) + 4 * ((p >> 1) & 3) + 16 * (p & 1); }
__host__ __device__ constexpr int ISIG(int k) { return 8 * (k & 3) + 2 * ((k >> 2) & 3) + (k >> 4); }
// register index remap: P=0 identity, P=1 ISIG-permuted storage
__host__ __device__ constexpr int MIDX(int P, int i) { return P ? ISIG(i) : i; }

// W_32^k constants, k = 0..21 : (cos(2pi k/32), -sin(2pi k/32))
__device__ __constant__ const float W32R[22] = {
    1.0f, 0.98078528f, 0.92387953f, 0.83146961f, 0.70710678f, 0.55557023f,
    0.38268343f, 0.19509032f, 0.0f, -0.19509032f, -0.38268343f, -0.55557023f,
    -0.70710678f, -0.83146961f, -0.92387953f, -0.98078528f, -1.0f,
    -0.98078528f, -0.92387953f, -0.83146961f, -0.70710678f, -0.55557023f };
__device__ __constant__ const float W32I[22] = {
    0.0f, -0.19509032f, -0.38268343f, -0.55557023f, -0.70710678f, -0.83146961f,
    -0.92387953f, -0.98078528f, -1.0f, -0.98078528f, -0.92387953f, -0.83146961f,
    -0.70710678f, -0.55557023f, -0.38268343f, -0.19509032f, 0.0f,
    0.19509032f, 0.38268343f, 0.55557023f, 0.70710678f, 0.83146961f };

__device__ __forceinline__ void bf_dif3(float2& a, float2& b, float2& c, float2& d,
                                        float2 w1, float2 w2, float2 w3) {
    float2 t0 = padd(a, c), t1 = psub(a, c), t2 = padd(b, d);
    float2 t3 = make_float2(b.y - d.y, d.x - b.x);   // -i*(b-d)
    a = padd(t0, t2);
    float2 o1 = padd(t1, t3), o2 = psub(t0, t2), o3 = psub(t1, t3);
    b = cmul(o1, w1); c = cmul(o2, w2); d = cmul(o3, w3);
}
__device__ __forceinline__ void bf_dif_nt(float2& a, float2& b, float2& c, float2& d) {
    float2 t0 = padd(a, c), t1 = psub(a, c), t2 = padd(b, d);
    float2 t3 = make_float2(b.y - d.y, d.x - b.x);
    a = padd(t0, t2); b = padd(t1, t3); c = psub(t0, t2); d = psub(t1, t3);
}

// In-place 32-pt DIF FFT with compile-time register remap P.
// Logical natural order in, SIG-permuted out (logical pos p at reg MIDX(P,p)).
template<int P>
__device__ __forceinline__ void fft32t(float2 v[32]) {
    bf_dif_nt(v[MIDX(P,0)], v[MIDX(P,8)], v[MIDX(P,16)], v[MIDX(P,24)]);
    #pragma unroll
    for (int i = 1; i < 8; i++)
        bf_dif3(v[MIDX(P,i)], v[MIDX(P,i+8)], v[MIDX(P,i+16)], v[MIDX(P,i+24)],
                make_float2(W32R[i], W32I[i]),
                make_float2(W32R[2 * i], W32I[2 * i]),
                make_float2(W32R[3 * i], W32I[3 * i]));
    #pragma unroll
    for (int blk = 0; blk < 4; blk++) {
        const int s = 8 * blk;
        bf_dif_nt(v[MIDX(P,s)], v[MIDX(P,s+2)], v[MIDX(P,s+4)], v[MIDX(P,s+6)]);
        bf_dif3(v[MIDX(P,s+1)], v[MIDX(P,s+3)], v[MIDX(P,s+5)], v[MIDX(P,s+7)],
                make_float2(W32R[4], W32I[4]),
                make_float2(W32R[8], W32I[8]),
                make_float2(W32R[12], W32I[12]));
    }
    #pragma unroll
    for (int u = 0; u < 16; u++) {
        float2 a = v[MIDX(P,2*u)], b = v[MIDX(P,2*u+1)];
        v[MIDX(P,2*u)]   = padd(a, b);
        v[MIDX(P,2*u+1)] = psub(a, b);
    }
}

// Multiply logical slot ISIG(m) (bin k1=m) by W_1024^{lane*m}; base A1 = W_1024^lane.
template<int P>
__device__ __forceinline__ void twmult(float2 v[32], float2 A1) {
    float2 A2 = cmul(A1, A1);
    float2 A3 = cmul(A2, A1);
    float2 A4 = cmul(A2, A2);
    float2 A5 = cmul(A4, A1);
    float2 A6 = cmul(A4, A2);
    float2 A7 = cmul(A4, A3);
    float2 B8  = cmul(A4, A4);
    float2 B16 = cmul(B8, B8);
    float2 B24 = cmul(B16, B8);
    float2 A[8] = { make_float2(1.f, 0.f), A1, A2, A3, A4, A5, A6, A7 };
    #pragma unroll
    for (int d = 1; d < 8; d++)
        v[MIDX(P,ISIG(d))] = cmul(v[MIDX(P,ISIG(d))], A[d]);
    v[MIDX(P,ISIG(8))]  = cmul(v[MIDX(P,ISIG(8))],  B8);
    v[MIDX(P,ISIG(16))] = cmul(v[MIDX(P,ISIG(16))], B16);
    v[MIDX(P,ISIG(24))] = cmul(v[MIDX(P,ISIG(24))], B24);
    #pragma unroll
    for (int d = 1; d < 8; d++) {
        v[MIDX(P,ISIG(8 + d))]  = cmul(v[MIDX(P,ISIG(8 + d))],  cmul(B8,  A[d]));
        v[MIDX(P,ISIG(16 + d))] = cmul(v[MIDX(P,ISIG(16 + d))], cmul(B16, A[d]));
        v[MIDX(P,ISIG(24 + d))] = cmul(v[MIDX(P,ISIG(24 + d))], cmul(B24, A[d]));
    }
}

// W[k] = gp*Zk + gm*conj(Zm); returns conj(W)
__device__ __forceinline__ float2 combW(float g0, float g1, float2 Zk, float2 Zm) {
    float gp = 0.5f * (g0 + g1), gm = 0.5f * (g0 - g1);
    return make_float2(fmaf(gp, Zk.x, gm * Zm.x),
                       fmaf(-gp, Zk.y, gm * Zm.y));
}

__device__ __forceinline__ float2 shfl2(float2 v, int src) {
    float2 r;
    r.x = __shfl_sync(0xffffffffu, v.x, src);
    r.y = __shfl_sync(0xffffffffu, v.y, src);
    return r;
}

__global__ __launch_bounds__(128)
void filtered_noise_kernel(const float* __restrict__ fb,     // (16,1,128,1001)
                           const float* __restrict__ noise,  // (16,1,256000)
                           float* __restrict__ out)          // (16,1,256000)
{
    __shared__ float2 tb[4][33 * 32];   // per-warp transpose buffer (33-stride pad)
    __shared__ float2 FP[4][NB];        // per-warp (g0,g1) band gains
    __shared__ float2 tw32s[32];        // W_1024^l, l<32
    __shared__ float  wint[1024];       // Hann * (1/1024)

    const int tid  = threadIdx.x;
    const int wid  = tid >> 5;
    const int lane = tid & 31;
    const int b    = blockIdx.y;
    const int pr   = blockIdx.x * 4 + wid;

    #pragma unroll
    for (int idx = tid; idx < 1024; idx += 128)
        wint[idx] = 0.5f * (1.0f - cospif((float)(2 * idx) * (1.0f / 1023.0f)))
                  * (1.0f / 1024.0f);
    if (tid < 32) {
        float sn, cs;
        sincospif(-(float)tid * (1.0f / 512.0f), &sn, &cs);
        tw32s[tid] = make_float2(cs, sn);
    }
    __syncthreads();
    if (pr >= NPAIR) return;

    const int  t0 = 2 * pr;
    const bool v1 = (t0 + 1) < TFR;

    float2* FPw = FP[wid];
    #pragma unroll
    for (int u = lane; u < NB; u += 32) {
        float g0 = fb[(b * NB + u) * TFR + t0];
        float g1 = v1 ? fb[(b * NB + u) * TFR + t0 + 1] : 0.0f;
        FPw[u] = make_float2(g0, g1);
    }

    float2* tbw = tb[wid];
    const int    base0 = t0 * HOP - 512;
    const size_t nOff  = (size_t)b * LOUT;
    const bool interior = (base0 >= 0) && (base0 + 1280 <= LOUT);
    const float2 A1 = tw32s[lane];

    // ---- load: v[n1] = z[32*n1 + lane], z = frame(t0) + i*frame(t1) ----
    float2 v[32];
    if (interior) {
        const float* np = noise + nOff + base0 + lane;
        #pragma unroll
        for (int n1 = 0; n1 < 32; n1++) {
            float xa = np[32 * n1];
            float xb = np[32 * n1 + HOP];
            v[n1] = make_float2(fmaf(xa, 2.0f, -1.0f), fmaf(xb, 2.0f, -1.0f));
        }
    } else {
        #pragma unroll
        for (int n1 = 0; n1 < 32; n1++) {
            int s0 = base0 + 32 * n1 + lane;
            int s1 = s0 + HOP;
            float xa = (s0 >= 0 && s0 < LOUT) ? fmaf(noise[nOff + s0], 2.0f, -1.0f) : 0.0f;
            float xb = (v1 && s1 >= 0 && s1 < LOUT) ? fmaf(noise[nOff + s1], 2.0f, -1.0f) : 0.0f;
            v[n1] = make_float2(xa, xb);
        }
    }

    // ================= forward four-step FFT =================
    fft32t<0>(v);             // over n1; reg p holds k1 = SIG(p)
    twmult<0>(v, A1);         // *= W_1024^{lane * k1}
    #pragma unroll
    for (int p = 0; p < 32; p++) tbw[33 * SIG(p) + lane] = v[p];
    __syncwarp();
    #pragma unroll
    for (int n2 = 0; n2 < 32; n2++) v[n2] = tbw[33 * lane + n2];
    fft32t<0>(v);             // reg q holds bin k = 32*SIG(q) + lane

    // ================= spectral combine, IN PLACE (bin-indexed regs) =================
    // partner of bin k: lane (32-l)&31, reg ISIG(31-SIG(q)). Each reg read once
    // (own + via shuffle, both before its write), written once.
    {
        const int pl = (32 - lane) & 31;
        #pragma unroll
        for (int sq = 0; sq < 16; sq++) {
            const int q = ISIG(sq), tq = ISIG(31 - sq);
            float2 pq  = shfl2(v[tq], pl);   // partner value for bin at reg q
            float2 ptq = shfl2(v[q],  pl);   // partner value for bin at reg tq
            if (lane != 0) {
                float2 gq  = FPw[(32 * sq + lane - 1) >> 2];
                float2 gtq = FPw[(32 * sq + 31 - lane) >> 2];
                float2 nq  = combW(gq.x,  gq.y,  v[q],  pq);
                float2 ntq = combW(gtq.x, gtq.y, v[tq], ptq);
                v[q]  = nq;
                v[tq] = ntq;
            }
        }
        if (lane == 0) {
            // bins k = 32*sq: pairs (sq, 32-sq) thread-local
            #pragma unroll
            for (int sq = 1; sq < 16; sq++) {
                const int qa = ISIG(sq), qb = ISIG(32 - sq);
                float2 A = v[qa], B = v[qb];
                float2 g = FPw[(32 * sq - 1) >> 2];
                v[qa] = combW(g.x, g.y, A, B);
                v[qb] = combW(g.x, g.y, B, A);
            }
            float2 g512 = FPw[127];
            v[ISIG(16)] = combW(g512.x, g512.y, v[ISIG(16)], v[ISIG(16)]);
            v[0] = make_float2(0.0f, 0.0f);   // DC (reg ISIG(0) = 0)
        }
    }

    // ================= inverse four-step (forward FFT of conj spectrum) =================
    // input c[n1] lives at reg ISIG(n1) -> use permuted register indexing (P=1)
    fft32t<1>(v);
    twmult<1>(v, A1);
    __syncwarp();             // WAR: forward transpose reads done in all lanes
    #pragma unroll
    for (int p = 0; p < 32; p++) tbw[33 * SIG(p) + lane] = v[MIDX(1, p)];
    __syncwarp();
    #pragma unroll
    for (int n2 = 0; n2 < 32; n2++) v[n2] = tbw[33 * lane + n2];
    fft32t<0>(v);             // reg q: time sample n = 32*SIG(q) + lane (x1024, conj)

    // ---- Hann window + FUSED overlap-add: rows h of frame0 and h-8 of frame1
    // target the same output word -> one atomic each (40 instead of 64) ----
    if (interior) {
        float* op = out + nOff + base0 + lane;
        #pragma unroll
        for (int h = 0; h < 40; h++) {
            float acc;
            if (h < 8)
                acc = v[ISIG(h)].x * wint[32 * h + lane];
            else if (h < 32)
                acc = fmaf(v[ISIG(h)].x, wint[32 * h + lane],
                           -v[ISIG(h - 8)].y * wint[32 * (h - 8) + lane]);
            else
                acc = -v[ISIG(h - 8)].y * wint[32 * (h - 8) + lane];
            atomicAdd(&op[32 * h], acc);
        }
    } else {
        #pragma unroll
        for (int h = 0; h < 40; h++) {
            float acc = 0.0f;
            if (h < 32)
                acc = v[ISIG(h)].x * wint[32 * h + lane];
            if (h >= 8 && v1)
                acc += -v[ISIG(h - 8)].y * wint[32 * (h - 8) + lane];
            int s = base0 + 32 * h + lane;
            if (s >= 0 && s < LOUT)
                atomicAdd(&out[nOff + s], acc);
        }
    }
}

extern "C" void kernel_launch(void* const* d_in, const int* in_sizes, int n_in,
                              void* d_out, int out_size)
{
    const float* fb    = (const float*)d_in[0];
    const float* noise = (const float*)d_in[1];
    float* out = (float*)d_out;

    cudaMemsetAsync(out, 0, (size_t)out_size * sizeof(float));

    dim3 grid((NPAIR + 3) / 4, 16);
    filtered_noise_kernel<<<grid, 128>>>(fb, noise, out);
}

// round 10
// speedup vs baseline: 1.6934x; 1.0358x over previous
#include <cuda_runtime.h>

#define HOP    256
#define NB     128
#define TFR    1001
#define LOUT   256000
#define NPAIR  501            // ceil(1001/2)

// ---- packed f32x2 ops (Blackwell) ----
__device__ __forceinline__ float2 padd(float2 a, float2 b) {
    float2 r;
    asm("add.rn.f32x2 %0, %1, %2;"
        : "=l"(reinterpret_cast<unsigned long long&>(r))
        : "l"(reinterpret_cast<unsigned long long&>(a)),
          "l"(reinterpret_cast<unsigned long long&>(b)));
    return r;
}
__device__ __forceinline__ float2 psub(float2 a, float2 b) {
    float2 r;
    asm("sub.rn.f32x2 %0, %1, %2;"
        : "=l"(reinterpret_cast<unsigned long long&>(r))
        : "l"(reinterpret_cast<unsigned long long&>(a)),
          "l"(reinterpret_cast<unsigned long long&>(b)));
    return r;
}
__device__ __forceinline__ float2 cmul(float2 a, float2 b) {
    return make_float2(fmaf(a.x, b.x, -a.y * b.y), fmaf(a.x, b.y, a.y * b.x));
}

// Output permutation of the local 32-pt DIF FFT (radix 4,4,2):
// position p = 8a + 2b + c  holds bin  k = a + 4b + 16c
__host__ __device__ constexpr int SIG(int p)  { return (p >> 3) + 4 * ((p >> 1) & 3) + 16 * (p & 1); }
__host__ __device__ constexpr int ISIG(int k) { return 8 * (k & 3) + 2 * ((k >> 2) & 3) + (k >> 4); }
// register index remap: P=0 identity, P=1 ISIG-permuted storage
__host__ __device__ constexpr int MIDX(int P, int i) { return P ? ISIG(i) : i; }

// W_32^k constants, k = 0..21 : (cos(2pi k/32), -sin(2pi k/32))
__device__ __constant__ const float W32R[22] = {
    1.0f, 0.98078528f, 0.92387953f, 0.83146961f, 0.70710678f, 0.55557023f,
    0.38268343f, 0.19509032f, 0.0f, -0.19509032f, -0.38268343f, -0.55557023f,
    -0.70710678f, -0.83146961f, -0.92387953f, -0.98078528f, -1.0f,
    -0.98078528f, -0.92387953f, -0.83146961f, -0.70710678f, -0.55557023f };
__device__ __constant__ const float W32I[22] = {
    0.0f, -0.19509032f, -0.38268343f, -0.55557023f, -0.70710678f, -0.83146961f,
    -0.92387953f, -0.98078528f, -1.0f, -0.98078528f, -0.92387953f, -0.83146961f,
    -0.70710678f, -0.55557023f, -0.38268343f, -0.19509032f, 0.0f,
    0.19509032f, 0.38268343f, 0.55557023f, 0.70710678f, 0.83146961f };

__device__ __forceinline__ void bf_dif3(float2& a, float2& b, float2& c, float2& d,
                                        float2 w1, float2 w2, float2 w3) {
    float2 t0 = padd(a, c), t1 = psub(a, c), t2 = padd(b, d);
    float2 t3 = make_float2(b.y - d.y, d.x - b.x);   // -i*(b-d)
    a = padd(t0, t2);
    float2 o1 = padd(t1, t3), o2 = psub(t0, t2), o3 = psub(t1, t3);
    b = cmul(o1, w1); c = cmul(o2, w2); d = cmul(o3, w3);
}
__device__ __forceinline__ void bf_dif_nt(float2& a, float2& b, float2& c, float2& d) {
    float2 t0 = padd(a, c), t1 = psub(a, c), t2 = padd(b, d);
    float2 t3 = make_float2(b.y - d.y, d.x - b.x);
    a = padd(t0, t2); b = padd(t1, t3); c = psub(t0, t2); d = psub(t1, t3);
}

// In-place 32-pt DIF FFT with compile-time register remap P.
template<int P>
__device__ __forceinline__ void fft32t(float2 v[32]) {
    bf_dif_nt(v[MIDX(P,0)], v[MIDX(P,8)], v[MIDX(P,16)], v[MIDX(P,24)]);
    #pragma unroll
    for (int i = 1; i < 8; i++)
        bf_dif3(v[MIDX(P,i)], v[MIDX(P,i+8)], v[MIDX(P,i+16)], v[MIDX(P,i+24)],
                make_float2(W32R[i], W32I[i]),
                make_float2(W32R[2 * i], W32I[2 * i]),
                make_float2(W32R[3 * i], W32I[3 * i]));
    #pragma unroll
    for (int blk = 0; blk < 4; blk++) {
        const int s = 8 * blk;
        bf_dif_nt(v[MIDX(P,s)], v[MIDX(P,s+2)], v[MIDX(P,s+4)], v[MIDX(P,s+6)]);
        bf_dif3(v[MIDX(P,s+1)], v[MIDX(P,s+3)], v[MIDX(P,s+5)], v[MIDX(P,s+7)],
                make_float2(W32R[4], W32I[4]),
                make_float2(W32R[8], W32I[8]),
                make_float2(W32R[12], W32I[12]));
    }
    #pragma unroll
    for (int u = 0; u < 16; u++) {
        float2 a = v[MIDX(P,2*u)], b = v[MIDX(P,2*u+1)];
        v[MIDX(P,2*u)]   = padd(a, b);
        v[MIDX(P,2*u+1)] = psub(a, b);
    }
}

// Multiply logical slot ISIG(m) (bin k1=m) by W_1024^{lane*m}; base A1 = W_1024^lane.
// Recurrence form: live twiddle state = {A1, A, B8, B16, B24} only.
template<int P>
__device__ __forceinline__ void twmult(float2 v[32], float2 A1) {
    float2 A2 = cmul(A1, A1);
    float2 A4 = cmul(A2, A2);
    float2 B8  = cmul(A4, A4);
    float2 B16 = cmul(B8, B8);
    float2 B24 = cmul(B16, B8);
    v[MIDX(P,ISIG(8))]  = cmul(v[MIDX(P,ISIG(8))],  B8);
    v[MIDX(P,ISIG(16))] = cmul(v[MIDX(P,ISIG(16))], B16);
    v[MIDX(P,ISIG(24))] = cmul(v[MIDX(P,ISIG(24))], B24);
    float2 A = A1;
    #pragma unroll
    for (int d = 1; d < 8; d++) {
        v[MIDX(P,ISIG(d))]      = cmul(v[MIDX(P,ISIG(d))],      A);
        v[MIDX(P,ISIG(8 + d))]  = cmul(v[MIDX(P,ISIG(8 + d))],  cmul(B8,  A));
        v[MIDX(P,ISIG(16 + d))] = cmul(v[MIDX(P,ISIG(16 + d))], cmul(B16, A));
        v[MIDX(P,ISIG(24 + d))] = cmul(v[MIDX(P,ISIG(24 + d))], cmul(B24, A));
        if (d < 7) A = cmul(A, A1);
    }
}

// W[k] = gp*Zk + gm*conj(Zm); returns conj(W)
__device__ __forceinline__ float2 combW(float g0, float g1, float2 Zk, float2 Zm) {
    float gp = 0.5f * (g0 + g1), gm = 0.5f * (g0 - g1);
    return make_float2(fmaf(gp, Zk.x, gm * Zm.x),
                       fmaf(-gp, Zk.y, gm * Zm.y));
}

__device__ __forceinline__ float2 shfl2(float2 v, int src) {
    float2 r;
    r.x = __shfl_sync(0xffffffffu, v.x, src);
    r.y = __shfl_sync(0xffffffffu, v.y, src);
    return r;
}

__global__ __launch_bounds__(128, 4)
void filtered_noise_kernel(const float* __restrict__ fb,     // (16,1,128,1001)
                           const float* __restrict__ noise,  // (16,1,256000)
                           float* __restrict__ out)          // (16,1,256000)
{
    __shared__ float2 tb[4][33 * 32];   // per-warp transpose buffer (33-stride pad)
    __shared__ float2 FP[4][NB];        // per-warp (g0,g1) band gains
    __shared__ float2 tw32s[32];        // W_1024^l, l<32
    __shared__ float  wint[1024];       // Hann * (1/1024)

    const int tid  = threadIdx.x;
    const int wid  = tid >> 5;
    const int lane = tid & 31;
    const int b    = blockIdx.y;
    const int pr   = blockIdx.x * 4 + wid;

    #pragma unroll
    for (int idx = tid; idx < 1024; idx += 128)
        wint[idx] = 0.5f * (1.0f - cospif((float)(2 * idx) * (1.0f / 1023.0f)))
                  * (1.0f / 1024.0f);
    if (tid < 32) {
        float sn, cs;
        sincospif(-(float)tid * (1.0f / 512.0f), &sn, &cs);
        tw32s[tid] = make_float2(cs, sn);
    }
    __syncthreads();
    if (pr >= NPAIR) return;

    const int  t0 = 2 * pr;
    const bool v1 = (t0 + 1) < TFR;

    float2* FPw = FP[wid];
    #pragma unroll
    for (int u = lane; u < NB; u += 32) {
        float g0 = fb[(b * NB + u) * TFR + t0];
        float g1 = v1 ? fb[(b * NB + u) * TFR + t0 + 1] : 0.0f;
        FPw[u] = make_float2(g0, g1);
    }

    float2* tbw = tb[wid];
    const int    base0 = t0 * HOP - 512;
    const size_t nOff  = (size_t)b * LOUT;
    const bool interior = (base0 >= 0) && (base0 + 1280 <= LOUT);
    const float2 A1 = tw32s[lane];

    // ---- load: v[n1] = z[32*n1 + lane], z = frame(t0) + i*frame(t1) ----
    float2 v[32];
    if (interior) {
        const float* np = noise + nOff + base0 + lane;
        #pragma unroll
        for (int n1 = 0; n1 < 32; n1++) {
            float xa = np[32 * n1];
            float xb = np[32 * n1 + HOP];
            v[n1] = make_float2(fmaf(xa, 2.0f, -1.0f), fmaf(xb, 2.0f, -1.0f));
        }
    } else {
        #pragma unroll
        for (int n1 = 0; n1 < 32; n1++) {
            int s0 = base0 + 32 * n1 + lane;
            int s1 = s0 + HOP;
            float xa = (s0 >= 0 && s0 < LOUT) ? fmaf(noise[nOff + s0], 2.0f, -1.0f) : 0.0f;
            float xb = (v1 && s1 >= 0 && s1 < LOUT) ? fmaf(noise[nOff + s1], 2.0f, -1.0f) : 0.0f;
            v[n1] = make_float2(xa, xb);
        }
    }

    // ================= forward four-step FFT =================
    fft32t<0>(v);             // over n1; reg p holds k1 = SIG(p)
    twmult<0>(v, A1);         // *= W_1024^{lane * k1}
    #pragma unroll
    for (int p = 0; p < 32; p++) tbw[33 * SIG(p) + lane] = v[p];
    __syncwarp();
    #pragma unroll
    for (int n2 = 0; n2 < 32; n2++) v[n2] = tbw[33 * lane + n2];
    fft32t<0>(v);             // reg q holds bin k = 32*SIG(q) + lane

    // ================= spectral combine, IN PLACE (bin-indexed regs) =================
    {
        const int pl = (32 - lane) & 31;
        #pragma unroll
        for (int sq = 0; sq < 16; sq++) {
            const int q = ISIG(sq), tq = ISIG(31 - sq);
            float2 pq  = shfl2(v[tq], pl);   // partner value for bin at reg q
            float2 ptq = shfl2(v[q],  pl);   // partner value for bin at reg tq
            if (lane != 0) {
                float2 gq  = FPw[(32 * sq + lane - 1) >> 2];
                float2 gtq = FPw[(32 * sq + 31 - lane) >> 2];
                float2 nq  = combW(gq.x,  gq.y,  v[q],  pq);
                float2 ntq = combW(gtq.x, gtq.y, v[tq], ptq);
                v[q]  = nq;
                v[tq] = ntq;
            }
        }
        if (lane == 0) {
            #pragma unroll
            for (int sq = 1; sq < 16; sq++) {
                const int qa = ISIG(sq), qb = ISIG(32 - sq);
                float2 A = v[qa], B = v[qb];
                float2 g = FPw[(32 * sq - 1) >> 2];
                v[qa] = combW(g.x, g.y, A, B);
                v[qb] = combW(g.x, g.y, B, A);
            }
            float2 g512 = FPw[127];
            v[ISIG(16)] = combW(g512.x, g512.y, v[ISIG(16)], v[ISIG(16)]);
            v[0] = make_float2(0.0f, 0.0f);   // DC (reg ISIG(0) = 0)
        }
    }

    // ================= inverse four-step (forward FFT of conj spectrum) =================
    fft32t<1>(v);
    twmult<1>(v, A1);
    __syncwarp();             // WAR: forward transpose reads done in all lanes
    #pragma unroll
    for (int p = 0; p < 32; p++) tbw[33 * SIG(p) + lane] = v[MIDX(1, p)];
    __syncwarp();
    #pragma unroll
    for (int n2 = 0; n2 < 32; n2++) v[n2] = tbw[33 * lane + n2];
    fft32t<0>(v);             // reg q: time sample n = 32*SIG(q) + lane (x1024, conj)

    // ---- Hann window + FUSED overlap-add (40 atomics instead of 64) ----
    const float* wp = wint + lane;
    if (interior) {
        float* op = out + nOff + base0 + lane;
        #pragma unroll
        for (int h = 0; h < 40; h++) {
            float acc;
            if (h < 8)
                acc = v[ISIG(h)].x * wp[32 * h];
            else if (h < 32)
                acc = fmaf(v[ISIG(h)].x, wp[32 * h],
                           -v[ISIG(h - 8)].y * wp[32 * (h - 8)]);
            else
                acc = -v[ISIG(h - 8)].y * wp[32 * (h - 8)];
            atomicAdd(&op[32 * h], acc);
        }
    } else {
        #pragma unroll
        for (int h = 0; h < 40; h++) {
            float acc = 0.0f;
            if (h < 32)
                acc = v[ISIG(h)].x * wp[32 * h];
            if (h >= 8 && v1)
                acc += -v[ISIG(h - 8)].y * wp[32 * (h - 8)];
            int s = base0 + 32 * h + lane;
            if (s >= 0 && s < LOUT)
                atomicAdd(&out[nOff + s], acc);
        }
    }
}

extern "C" void kernel_launch(void* const* d_in, const int* in_sizes, int n_in,
                              void* d_out, int out_size)
{
    const float* fb    = (const float*)d_in[0];
    const float* noise = (const float*)d_in[1];
    float* out = (float*)d_out;

    cudaMemsetAsync(out, 0, (size_t)out_size * sizeof(float));

    dim3 grid((NPAIR + 3) / 4, 16);
    filtered_noise_kernel<<<grid, 128>>>(fb, noise, out);
}